// round 15
// baseline (speedup 1.0000x reference)
#include <cuda_runtime.h>
#include <cuda_fp16.h>

// SpatialTransformer: 3D trilinear warp, smem-tiled, ILP-4, fp16 z-pair tile,
// clamp-free inner loop (R14), with z-tile-32 warp geometry: output tile
// 16(x) x 8(y) x 32(z), warp = 8 z-quads x 4 y-rows so each trf LDG.128
// covers 4 rows x 384B (3 full lines) and each out STG.128 covers 4 rows x
// 128B (1 aligned line each).
//
// Tile entry (x,y,e) = __half2( v[z0-2+e], v[z0-2+e+1] ), e in [0..35],
// layout [x][y][e], stride 38 -> 20x12x38 half2 = 36.5 KB, 5 blocks/SM.
// Halo-clamped fill makes the hot loop clamp-free; floors outside the tile
// (~1.2%) take the exact fp32 fully-clamped global fallback.

#define DX 160
#define DY 192
#define DZ 160
#define NB 2
#define TSX 16
#define TSY 8
#define TSZ 32
#define SX 20           // x entries: [x0-2 .. x0+17]
#define SY 12           // y entries: [y0-2 .. y0+9]
#define SZE 36          // z entries: e in [0..35] -> iz0 in [z0-2 .. z0+33]
#define SZPH 38         // padded entry stride (152B rows, 8B-aligned)
#define SHALF2 (SX*SY*SZPH)   // 9120 half2 = 36480 B

extern __shared__ __half2 tile[];

__device__ __forceinline__ int iclamp(int v, int hi) {
    return min(max(v, 0), hi);
}

__device__ __forceinline__ unsigned pack_h2(float a, float b) {
    __half2 h = __floats2half2_rn(a, b);
    return *reinterpret_cast<unsigned*>(&h);
}

// Exact reference math, fully clamped, fp32 global gather (rare path).
__device__ __forceinline__ float fallback_exact(
    const float* __restrict__ v, float sx, float sy, float sz)
{
    float lx = fminf(fmaxf(sx, 0.0f), (float)(DX - 1));
    float ly = fminf(fmaxf(sy, 0.0f), (float)(DY - 1));
    float lz = fminf(fmaxf(sz, 0.0f), (float)(DZ - 1));
    int ix0 = __float2int_rd(lx);
    int iy0 = __float2int_rd(ly);
    int iz0 = __float2int_rd(lz);
    int ix1 = min(ix0 + 1, DX - 1);
    int iy1 = min(iy0 + 1, DY - 1);
    int iz1 = min(iz0 + 1, DZ - 1);
    float wx1 = (float)ix1 - lx, wy1 = (float)iy1 - ly, wz1 = (float)iz1 - lz;
    float wx0 = 1.0f - wx1, wy0 = 1.0f - wy1, wz0 = 1.0f - wz1;
    const float* p00 = v + ((size_t)ix0 * DY + iy0) * DZ;
    const float* p01 = v + ((size_t)ix0 * DY + iy1) * DZ;
    const float* p10 = v + ((size_t)ix1 * DY + iy0) * DZ;
    const float* p11 = v + ((size_t)ix1 * DY + iy1) * DZ;
    float c00 = __ldg(p00 + iz0) * wz1 + __ldg(p00 + iz1) * wz0;
    float c01 = __ldg(p01 + iz0) * wz1 + __ldg(p01 + iz1) * wz0;
    float c10 = __ldg(p10 + iz0) * wz1 + __ldg(p10 + iz1) * wz0;
    float c11 = __ldg(p11 + iz0) * wz1 + __ldg(p11 + iz1) * wz0;
    float c0 = c00 * wy1 + c01 * wy0;
    float c1 = c10 * wy1 + c11 * wy0;
    return c0 * wx1 + c1 * wx0;
}

__global__ __launch_bounds__(256, 5)
void warp_h2z32_kernel(const float* __restrict__ vol,
                       const float* __restrict__ trf,
                       float* __restrict__ out)
{
    const int tid = threadIdx.x;
    const int b  = blockIdx.z / (DX / TSX);
    const int x0 = (blockIdx.z % (DX / TSX)) * TSX;
    const int y0 = blockIdx.y * TSY;
    const int z0 = blockIdx.x * TSZ;

    const float* __restrict__ v = vol + (size_t)b * (DX * DY * DZ);
    const int xlo = x0 - 2, ylo = y0 - 2, zent0 = z0 - 2;  // entry 0 -> iz0=z0-2

    // ---------------- cooperative tile fill (clamped halo) ----------------
    if (z0 - 4 >= 0 && z0 + 35 <= DZ - 1) {
        // Read aligned span v[z0-4 .. z0+35] = 10 float4 per (x,y) row.
        // Chunk c holds src[4c..4c+3]; entry e = iz0-(z0-2) gets pair
        // (src[e+2], src[e+3]); chunk c covers entries 4c-2 .. 4c+1.
        // uint2 stores at even entry offsets (row stride 152B -> 8B-aligned).
        for (int idx = tid; idx < SX * SY * 10; idx += 256) {
            int c   = idx % 10;
            int row = idx / 10;
            int py  = row % SY;
            int px  = row / SY;
            int gx  = iclamp(xlo + px, DX - 1);
            int gy  = iclamp(ylo + py, DY - 1);
            const float* src = v + ((size_t)gx * DY + gy) * DZ + (z0 - 4);
            float4 val = __ldg(reinterpret_cast<const float4*>(src) + c);
            __half2* rowp = &tile[(px * SY + py) * SZPH];
            if (c == 0) {
                // entries 0:(z,w) 1:(w,next)
                float nxt = __ldg(src + 4);
                uint2 p; p.x = pack_h2(val.z, val.w); p.y = pack_h2(val.w, nxt);
                *reinterpret_cast<uint2*>(rowp + 0) = p;
            } else if (c == 9) {
                // entries 34:(x,y) 35:(y,z)
                uint2 p; p.x = pack_h2(val.x, val.y); p.y = pack_h2(val.y, val.z);
                *reinterpret_cast<uint2*>(rowp + 34) = p;
            } else {
                float nxt = __ldg(src + c * 4 + 4);
                uint2 p0; p0.x = pack_h2(val.x, val.y); p0.y = pack_h2(val.y, val.z);
                uint2 p1; p1.x = pack_h2(val.z, val.w); p1.y = pack_h2(val.w, nxt);
                *reinterpret_cast<uint2*>(rowp + (c * 4 - 2)) = p0;
                *reinterpret_cast<uint2*>(rowp + (c * 4    )) = p1;
            }
        }
    } else {
        // z-border: scalar, clamp baked into each pair.
        for (int idx = tid; idx < SX * SY * SZE; idx += 256) {
            int pz = idx % SZE;
            int r  = idx / SZE;
            int py = r % SY;
            int px = r / SY;
            int gx = iclamp(xlo + px, DX - 1);
            int gy = iclamp(ylo + py, DY - 1);
            const float* rowp = v + ((size_t)gx * DY + gy) * DZ;
            int gz0 = iclamp(zent0 + pz,     DZ - 1);
            int gz1 = iclamp(zent0 + pz + 1, DZ - 1);
            float a  = __ldg(rowp + gz0);
            float b2 = __ldg(rowp + gz1);
            tile[(px * SY + py) * SZPH + pz] = __floats2half2_rn(a, b2);
        }
    }
    __syncthreads();

    // ---------------- per-voxel warp, 4 z-voxels per thread ----------------
    const int zg = tid & 7;            // z quad (0..7)
    const int vy = (tid >> 3) & 7;     // 0..7
    const int xs = tid >> 6;           // 0..3
    const int gy = y0 + vy;
    const int zb = z0 + zg * 4;

    unsigned g = (unsigned)((((b * DX + x0 + xs) * DY + gy) * (DZ / 4))
                            + (z0 >> 2) + zg);
    const unsigned gstep = (unsigned)(DY * DZ);
    const float fgy = (float)gy;

    const float4* __restrict__ trf4 = reinterpret_cast<const float4*>(trf);
    float4* __restrict__ out4 = reinterpret_cast<float4*>(out);

#pragma unroll 1
    for (int it = 0; it < 4; ++it, g += gstep) {
        const float fgx = (float)(x0 + it * 4 + xs);

        float4 t0 = __ldg(&trf4[g * 3u + 0u]);
        float4 t1 = __ldg(&trf4[g * 3u + 1u]);
        float4 t2 = __ldg(&trf4[g * 3u + 2u]);

        float tx[4] = {t0.x, t0.w, t1.z, t2.y};
        float ty[4] = {t0.y, t1.x, t1.w, t2.z};
        float tz[4] = {t0.z, t1.y, t2.x, t2.w};

        float4 res;
        float* rp = reinterpret_cast<float*>(&res);

#pragma unroll
        for (int j = 0; j < 4; ++j) {
            // UNCLAMPED sample location (halo-clamped tile subsumes clamps)
            float lx = fgx + tx[j];
            float ly = fgy + ty[j];
            float lz = (float)(zb + j) + tz[j];

            float fx0 = floorf(lx);
            float fy0 = floorf(ly);
            float fz0 = floorf(lz);

            float wx0 = lx - fx0, wx1 = 1.0f - wx0;
            float wy0 = ly - fy0, wy1 = 1.0f - wy0;
            float wz0 = lz - fz0, wz1 = 1.0f - wz0;

            int ix0 = (int)fx0;
            int iy0 = (int)fy0;
            int iz0 = (int)fz0;

            unsigned sux = (unsigned)(ix0 - xlo);
            unsigned suy = (unsigned)(iy0 - ylo);
            unsigned suz = (unsigned)(iz0 - zent0);

            if (sux <= (unsigned)(SX - 2) &&
                suy <= (unsigned)(SY - 2) &&
                suz <= (unsigned)(SZE - 1)) {
                const __half2* t00 = &tile[(sux * SY + suy) * SZPH + suz];
                float2 f00 = __half22float2(t00[0]);
                float2 f01 = __half22float2(t00[SZPH]);             // +y
                float2 f10 = __half22float2(t00[SY * SZPH]);        // +x
                float2 f11 = __half22float2(t00[SY * SZPH + SZPH]); // +x+y
                float c00 = f00.x * wz1 + f00.y * wz0;
                float c01 = f01.x * wz1 + f01.y * wz0;
                float c10 = f10.x * wz1 + f10.y * wz0;
                float c11 = f11.x * wz1 + f11.y * wz0;
                float c0 = c00 * wy1 + c01 * wy0;
                float c1 = c10 * wy1 + c11 * wy0;
                rp[j] = c0 * wx1 + c1 * wx0;
            } else {
                rp[j] = fallback_exact(v, lx, ly, lz);
            }
        }

        out4[g] = res;
    }
}

extern "C" void kernel_launch(void* const* d_in, const int* in_sizes, int n_in,
                              void* d_out, int out_size)
{
    const float* vol = (const float*)d_in[0];
    const float* trf = (const float*)d_in[1];
    float* out = (float*)d_out;

    cudaFuncSetAttribute(warp_h2z32_kernel,
                         cudaFuncAttributeMaxDynamicSharedMemorySize,
                         SHALF2 * (int)sizeof(__half2));

    dim3 grid(DZ / TSZ, DY / TSY, NB * (DX / TSX));  // (5, 24, 20) = 2400
    warp_h2z32_kernel<<<grid, 256, SHALF2 * sizeof(__half2)>>>(vol, trf, out);
}

// round 16
// speedup vs baseline: 1.0374x; 1.0374x over previous
#include <cuda_runtime.h>
#include <cuda_fp16.h>

// SpatialTransformer: 3D trilinear warp, smem-tiled, ILP-4, fp16 z-pair tile,
// clamp-free inner loop, z-tile-32 warp geometry (R15), with PACKED fp16
// y/x lerp: the half2 tile entries are (z, z+1) pairs, so the y- and x-
// interpolations run as HMUL2/HFMA2 on both z-planes at once; only the final
// z lerp is fp32. Cuts ~7 issued instructions per voxel in an issue-bound
// kernel. Out-of-tile floors (~1.2%) use the exact fp32 clamped fallback.

#define DX 160
#define DY 192
#define DZ 160
#define NB 2
#define TSX 16
#define TSY 8
#define TSZ 32
#define SX 20           // x entries: [x0-2 .. x0+17]
#define SY 12           // y entries: [y0-2 .. y0+9]
#define SZE 36          // z entries: e in [0..35] -> iz0 in [z0-2 .. z0+33]
#define SZPH 38         // padded entry stride (152B rows, 8B-aligned)
#define SHALF2 (SX*SY*SZPH)   // 9120 half2 = 36480 B

extern __shared__ __half2 tile[];

__device__ __forceinline__ int iclamp(int v, int hi) {
    return min(max(v, 0), hi);
}

__device__ __forceinline__ unsigned pack_h2(float a, float b) {
    __half2 h = __floats2half2_rn(a, b);
    return *reinterpret_cast<unsigned*>(&h);
}

// Exact reference math, fully clamped, fp32 global gather (rare path).
__device__ __forceinline__ float fallback_exact(
    const float* __restrict__ v, float sx, float sy, float sz)
{
    float lx = fminf(fmaxf(sx, 0.0f), (float)(DX - 1));
    float ly = fminf(fmaxf(sy, 0.0f), (float)(DY - 1));
    float lz = fminf(fmaxf(sz, 0.0f), (float)(DZ - 1));
    int ix0 = __float2int_rd(lx);
    int iy0 = __float2int_rd(ly);
    int iz0 = __float2int_rd(lz);
    int ix1 = min(ix0 + 1, DX - 1);
    int iy1 = min(iy0 + 1, DY - 1);
    int iz1 = min(iz0 + 1, DZ - 1);
    float wx1 = (float)ix1 - lx, wy1 = (float)iy1 - ly, wz1 = (float)iz1 - lz;
    float wx0 = 1.0f - wx1, wy0 = 1.0f - wy1, wz0 = 1.0f - wz1;
    const float* p00 = v + ((size_t)ix0 * DY + iy0) * DZ;
    const float* p01 = v + ((size_t)ix0 * DY + iy1) * DZ;
    const float* p10 = v + ((size_t)ix1 * DY + iy0) * DZ;
    const float* p11 = v + ((size_t)ix1 * DY + iy1) * DZ;
    float c00 = __ldg(p00 + iz0) * wz1 + __ldg(p00 + iz1) * wz0;
    float c01 = __ldg(p01 + iz0) * wz1 + __ldg(p01 + iz1) * wz0;
    float c10 = __ldg(p10 + iz0) * wz1 + __ldg(p10 + iz1) * wz0;
    float c11 = __ldg(p11 + iz0) * wz1 + __ldg(p11 + iz1) * wz0;
    float c0 = c00 * wy1 + c01 * wy0;
    float c1 = c10 * wy1 + c11 * wy0;
    return c0 * wx1 + c1 * wx0;
}

__global__ __launch_bounds__(256, 5)
void warp_h2lerp_kernel(const float* __restrict__ vol,
                        const float* __restrict__ trf,
                        float* __restrict__ out)
{
    const int tid = threadIdx.x;
    const int b  = blockIdx.z / (DX / TSX);
    const int x0 = (blockIdx.z % (DX / TSX)) * TSX;
    const int y0 = blockIdx.y * TSY;
    const int z0 = blockIdx.x * TSZ;

    const float* __restrict__ v = vol + (size_t)b * (DX * DY * DZ);
    const int xlo = x0 - 2, ylo = y0 - 2, zent0 = z0 - 2;

    // ---------------- cooperative tile fill (clamped halo) ----------------
    if (z0 - 4 >= 0 && z0 + 35 <= DZ - 1) {
        for (int idx = tid; idx < SX * SY * 10; idx += 256) {
            int c   = idx % 10;
            int row = idx / 10;
            int py  = row % SY;
            int px  = row / SY;
            int gx  = iclamp(xlo + px, DX - 1);
            int gy  = iclamp(ylo + py, DY - 1);
            const float* src = v + ((size_t)gx * DY + gy) * DZ + (z0 - 4);
            float4 val = __ldg(reinterpret_cast<const float4*>(src) + c);
            __half2* rowp = &tile[(px * SY + py) * SZPH];
            if (c == 0) {
                float nxt = __ldg(src + 4);
                uint2 p; p.x = pack_h2(val.z, val.w); p.y = pack_h2(val.w, nxt);
                *reinterpret_cast<uint2*>(rowp + 0) = p;
            } else if (c == 9) {
                uint2 p; p.x = pack_h2(val.x, val.y); p.y = pack_h2(val.y, val.z);
                *reinterpret_cast<uint2*>(rowp + 34) = p;
            } else {
                float nxt = __ldg(src + c * 4 + 4);
                uint2 p0; p0.x = pack_h2(val.x, val.y); p0.y = pack_h2(val.y, val.z);
                uint2 p1; p1.x = pack_h2(val.z, val.w); p1.y = pack_h2(val.w, nxt);
                *reinterpret_cast<uint2*>(rowp + (c * 4 - 2)) = p0;
                *reinterpret_cast<uint2*>(rowp + (c * 4    )) = p1;
            }
        }
    } else {
        for (int idx = tid; idx < SX * SY * SZE; idx += 256) {
            int pz = idx % SZE;
            int r  = idx / SZE;
            int py = r % SY;
            int px = r / SY;
            int gx = iclamp(xlo + px, DX - 1);
            int gy = iclamp(ylo + py, DY - 1);
            const float* rowp = v + ((size_t)gx * DY + gy) * DZ;
            int gz0 = iclamp(zent0 + pz,     DZ - 1);
            int gz1 = iclamp(zent0 + pz + 1, DZ - 1);
            float a  = __ldg(rowp + gz0);
            float b2 = __ldg(rowp + gz1);
            tile[(px * SY + py) * SZPH + pz] = __floats2half2_rn(a, b2);
        }
    }
    __syncthreads();

    // ---------------- per-voxel warp, 4 z-voxels per thread ----------------
    const int zg = tid & 7;            // z quad (0..7)
    const int vy = (tid >> 3) & 7;     // 0..7
    const int xs = tid >> 6;           // 0..3
    const int gy = y0 + vy;
    const int zb = z0 + zg * 4;

    unsigned g = (unsigned)((((b * DX + x0 + xs) * DY + gy) * (DZ / 4))
                            + (z0 >> 2) + zg);
    const unsigned gstep = (unsigned)(DY * DZ);
    const float fgy = (float)gy;
    const __half2 oneh = __float2half2_rn(1.0f);

    const float4* __restrict__ trf4 = reinterpret_cast<const float4*>(trf);
    float4* __restrict__ out4 = reinterpret_cast<float4*>(out);

#pragma unroll 1
    for (int it = 0; it < 4; ++it, g += gstep) {
        const float fgx = (float)(x0 + it * 4 + xs);

        float4 t0 = __ldg(&trf4[g * 3u + 0u]);
        float4 t1 = __ldg(&trf4[g * 3u + 1u]);
        float4 t2 = __ldg(&trf4[g * 3u + 2u]);

        float tx[4] = {t0.x, t0.w, t1.z, t2.y};
        float ty[4] = {t0.y, t1.x, t1.w, t2.z};
        float tz[4] = {t0.z, t1.y, t2.x, t2.w};

        float4 res;
        float* rp = reinterpret_cast<float*>(&res);

#pragma unroll
        for (int j = 0; j < 4; ++j) {
            // UNCLAMPED sample location (halo-clamped tile subsumes clamps)
            float lx = fgx + tx[j];
            float ly = fgy + ty[j];
            float lz = (float)(zb + j) + tz[j];

            float fx0 = floorf(lx);
            float fy0 = floorf(ly);
            float fz0 = floorf(lz);

            int ix0 = (int)fx0;
            int iy0 = (int)fy0;
            int iz0 = (int)fz0;

            unsigned sux = (unsigned)(ix0 - xlo);
            unsigned suy = (unsigned)(iy0 - ylo);
            unsigned suz = (unsigned)(iz0 - zent0);

            if (sux <= (unsigned)(SX - 2) &&
                suy <= (unsigned)(SY - 2) &&
                suz <= (unsigned)(SZE - 1)) {
                float wz0 = lz - fz0, wz1 = 1.0f - wz0;
                __half2 wy0h = __float2half2_rn(ly - fy0);
                __half2 wx0h = __float2half2_rn(lx - fx0);
                __half2 wy1h = __hsub2(oneh, wy0h);
                __half2 wx1h = __hsub2(oneh, wx0h);

                const __half2* t00 = &tile[(sux * SY + suy) * SZPH + suz];
                __half2 p00 = t00[0];
                __half2 p01 = t00[SZPH];              // +y
                __half2 p10 = t00[SY * SZPH];         // +x
                __half2 p11 = t00[SY * SZPH + SZPH];  // +x+y

                // y-lerp and x-lerp in packed fp16 (both z-planes at once)
                __half2 a0 = __hfma2(p01, wy0h, __hmul2(p00, wy1h));
                __half2 a1 = __hfma2(p11, wy0h, __hmul2(p10, wy1h));
                __half2 cc = __hfma2(a1, wx0h, __hmul2(a0, wx1h));

                float2 f = __half22float2(cc);
                rp[j] = f.x * wz1 + f.y * wz0;        // final z-lerp in fp32
            } else {
                rp[j] = fallback_exact(v, lx, ly, lz);
            }
        }

        out4[g] = res;
    }
}

extern "C" void kernel_launch(void* const* d_in, const int* in_sizes, int n_in,
                              void* d_out, int out_size)
{
    const float* vol = (const float*)d_in[0];
    const float* trf = (const float*)d_in[1];
    float* out = (float*)d_out;

    cudaFuncSetAttribute(warp_h2lerp_kernel,
                         cudaFuncAttributeMaxDynamicSharedMemorySize,
                         SHALF2 * (int)sizeof(__half2));

    dim3 grid(DZ / TSZ, DY / TSY, NB * (DX / TSX));  // (5, 24, 20) = 2400
    warp_h2lerp_kernel<<<grid, 256, SHALF2 * sizeof(__half2)>>>(vol, trf, out);
}